// round 7
// baseline (speedup 1.0000x reference)
#include <cuda_runtime.h>
#include <math.h>

#define BB 8
#define NN 8192
#define MM 4096
#define HH 128
#define WW 128

#define G    64
#define GC   (G * G)           // 4096 cells per batch
#define BTPB 1024
#define PPT  (NN / BTPB)       // 8 points per thread
#define QPT  (MM / BTPB)       // 4 queries per thread
#define CPT  (GC / BTPB)       // 4 cells per thread

#define QTPB 224               // query block threads (7 warps)
#define QPB  216               // queries per block -> grid 152 (one wave, all SMs)

__device__ float  g_mean[BB];
__device__ int    g_starts[BB * (GC + 1)];
__device__ float4 g_pts[BB * NN];   // cell-sorted points: x, y, 0, orig-idx bits
__device__ float4 g_q[BB * MM];     // cell-sorted queries: x, y, 0, orig-m bits

__device__ __forceinline__ int cell_of(float v) {
    int c = (int)(v * (float)G);
    return min(max(c, 0), G - 1);
}

// exclusive scan of GC counts in scnt[], leaves cursors in scnt, optionally writes starts
__device__ __forceinline__ void scan_counts(int* scnt, int* swscan, int tid,
                                            int lane, int wrp, int* starts) {
    int cnt[CPT], cur[CPT];
    int sum = 0;
    #pragma unroll
    for (int i = 0; i < CPT; ++i) { cnt[i] = scnt[tid * CPT + i]; sum += cnt[i]; }

    int v = sum;
    #pragma unroll
    for (int o = 1; o < 32; o <<= 1) {
        int n = __shfl_up_sync(0xffffffffu, v, o);
        if (lane >= o) v += n;
    }
    if (lane == 31) swscan[wrp] = v;
    __syncthreads();
    if (tid < 32) {
        int w = swscan[tid];
        #pragma unroll
        for (int o = 1; o < 32; o <<= 1) {
            int n = __shfl_up_sync(0xffffffffu, w, o);
            if (tid >= o) w += n;
        }
        swscan[tid] = w;
    }
    __syncthreads();
    int off = v - sum + (wrp ? swscan[wrp - 1] : 0);

    #pragma unroll
    for (int i = 0; i < CPT; ++i) {
        if (starts) starts[tid * CPT + i] = off;
        cur[i] = off;
        off += cnt[i];
    }
    __syncthreads();
    #pragma unroll
    for (int i = 0; i < CPT; ++i) scnt[tid * CPT + i] = cur[i];
    __syncthreads();
}

// ---------- build: 2 independent blocks per batch ----------
__global__ void __launch_bounds__(BTPB) build_kernel(
    const float* __restrict__ xc_off,   // (B,N,2)
    const float* __restrict__ yc_on,    // (B,H,W)
    const float* __restrict__ xt)       // (B,M,2)
{
    const int b    = blockIdx.x >> 1;
    const int role = blockIdx.x & 1;
    const int tid  = threadIdx.x;
    const int lane = tid & 31, wrp = tid >> 5;

    __shared__ int scnt[GC];
    __shared__ int swscan[32];

    #pragma unroll
    for (int i = 0; i < CPT; ++i) scnt[tid + i * BTPB] = 0;

    if (role == 0) {
        float2 pt[PPT];
        int    pc[PPT];
        const float2* cpts = (const float2*)(xc_off + (size_t)b * NN * 2);
        #pragma unroll
        for (int k = 0; k < PPT; ++k) {
            pt[k] = cpts[tid + k * BTPB];
            pc[k] = cell_of(pt[k].x) * G + cell_of(pt[k].y);
        }
        __syncthreads();
        #pragma unroll
        for (int k = 0; k < PPT; ++k) atomicAdd(&scnt[pc[k]], 1);
        __syncthreads();

        scan_counts(scnt, swscan, tid, lane, wrp, g_starts + b * (GC + 1));
        if (tid == 0) g_starts[b * (GC + 1) + GC] = NN;

        float4* dst = g_pts + (size_t)b * NN;
        #pragma unroll
        for (int k = 0; k < PPT; ++k) {
            int pos = atomicAdd(&scnt[pc[k]], 1);
            dst[pos] = make_float4(pt[k].x, pt[k].y, 0.f, __int_as_float(tid + k * BTPB));
        }
    } else {
        __shared__ float swsum[32];
        {
            const float* p = yc_on + (size_t)b * HH * WW;
            float s = 0.f;
            #pragma unroll
            for (int k = 0; k < (HH * WW) / BTPB; ++k) s += p[tid + k * BTPB];
            #pragma unroll
            for (int o = 16; o; o >>= 1) s += __shfl_down_sync(0xffffffffu, s, o);
            if (lane == 0) swsum[wrp] = s;
        }

        float2 qt[QPT];
        int    qc[QPT];
        const float2* q = (const float2*)(xt + (size_t)b * MM * 2);
        #pragma unroll
        for (int k = 0; k < QPT; ++k) {
            qt[k] = q[tid + k * BTPB];
            qc[k] = cell_of(qt[k].x) * G + cell_of(qt[k].y);
        }
        __syncthreads();
        if (tid < 32) {
            float s = swsum[tid];
            #pragma unroll
            for (int o = 16; o; o >>= 1) s += __shfl_down_sync(0xffffffffu, s, o);
            if (tid == 0) g_mean[b] = s * (1.0f / (HH * WW));
        }
        #pragma unroll
        for (int k = 0; k < QPT; ++k) atomicAdd(&scnt[qc[k]], 1);
        __syncthreads();

        scan_counts(scnt, swscan, tid, lane, wrp, (int*)0);

        float4* dst = g_q + (size_t)b * MM;
        #pragma unroll
        for (int k = 0; k < QPT; ++k) {
            int pos = atomicAdd(&scnt[qc[k]], 1);
            dst[pos] = make_float4(qt[k].x, qt[k].y, 0.f, __int_as_float(tid + k * BTPB));
        }
    }
}

// scan full square of half-width r around (qcx,qcy), row-pipelined.
// comparator is lexicographic-min over (d2, idx) -> idempotent, rescans safe.
__device__ __forceinline__ void scan_square(
    const float2 p, const int* __restrict__ starts, const float4* __restrict__ pts,
    int qcx, int qcy, int r, float& best, int& bidx)
{
    const int ilo = max(qcx - r, 0), ihi = min(qcx + r, G - 1);
    const int jlo = max(qcy - r, 0), jhi = min(qcy + r, G - 1);
    int i = ilo;
    int s = starts[i * G + jlo];
    int e = starts[i * G + jhi + 1];
    for (;;) {
        const bool more = (i < ihi);
        int sn = 0, en = 0;
        if (more) {                       // prefetch next row's bounds (overlaps scan)
            sn = starts[(i + 1) * G + jlo];
            en = starts[(i + 1) * G + jhi + 1];
        }
        #pragma unroll 2
        for (int k = s; k < e; ++k) {
            float4 c = pts[k];
            float dx = p.x - c.x;
            float dy = p.y - c.y;
            float d2 = __fadd_rn(__fmul_rn(dx, dx), __fmul_rn(dy, dy));
            int   idx = __float_as_int(c.w);
            if (d2 < best || (d2 == best && idx < bidx)) { best = d2; bidx = idx; }
        }
        if (!more) break;
        s = sn; e = en; ++i;
    }
}

// ---------------- query: grid NN (sorted queries) + bilinear + mix ----------------
__global__ void __launch_bounds__(QTPB) query_kernel(
    const float* __restrict__ yc_off,
    const float* __restrict__ yc_on,
    const float* __restrict__ logit,
    float* __restrict__ out)
{
    const int t = blockIdx.x * QPB + threadIdx.x;
    if (threadIdx.x >= QPB || t >= BB * MM) return;
    const int b = t / MM;

    const float4 q = g_q[t];
    const float2 p = make_float2(q.x, q.y);
    const int    m = __float_as_int(q.w);

    const int*    starts = g_starts + b * (GC + 1);
    const float4* pts    = g_pts + (size_t)b * NN;

    // ---- bilinear first: its loads overlap the NN-scan latency ----
    float yt_on;
    {
        float x = p.x, y = p.y;
        bool oob = (x < 0.0f) || (x > 1.0f) || (y < 0.0f) || (y > 1.0f);
        float fx = x * 127.0f;
        float fy = y * 127.0f;
        int ix = (int)floorf(fx);
        int iy = (int)floorf(fy);
        ix = min(max(ix, 0), 126);
        iy = min(max(iy, 0), 126);
        float wx = fx - (float)ix;
        float wy = fy - (float)iy;

        const float* vv = yc_on + ((size_t)b * HH + ix) * WW + iy;
        float v00 = vv[0];
        float v01 = vv[1];
        float v10 = vv[WW];
        float v11 = vv[WW + 1];

        yt_on = (1.0f - wx) * (1.0f - wy) * v00
              + (1.0f - wx) * wy          * v01
              + wx          * (1.0f - wy) * v10
              + wx          * wy          * v11;
        if (oob) yt_on = g_mean[b];
    }

    const float h = 1.0f / (float)G;
    const int qcx = cell_of(p.x);
    const int qcy = cell_of(p.y);

    float best = 3.402823466e+38f;
    int   bidx = 0x7fffffff;

    // initial half-width: NN distance >= distance d0 from p to [0,1]^2,
    // so the certifying square must reach ~d0 past the clamped cell.
    int r;
    {
        float dx0 = fmaxf(fmaxf(-p.x, p.x - 1.0f), 0.0f);
        float dy0 = fmaxf(fmaxf(-p.y, p.y - 1.0f), 0.0f);
        float d0sq = dx0 * dx0 + dy0 * dy0;
        r = 1;
        if (d0sq > 0.0f) r = (int)ceilf(sqrtf(d0sq) * (float)G) + 2;
        r = min(r, G);
    }

    scan_square(p, starts, pts, qcx, qcy, r, best, bidx);

    // bound-certify; rare expansion rescans the grown square (idempotent)
    for (;;) {
        float lox = (float)(qcx - r) * h,  hix = (float)(qcx + r + 1) * h;
        float loy = (float)(qcy - r) * h,  hiy = (float)(qcy + r + 1) * h;
        float bnd = 3.402823466e+38f;
        if (lox > 0.f) bnd = fminf(bnd, p.x - lox);
        if (hix < 1.f) bnd = fminf(bnd, hix - p.x);
        if (loy > 0.f) bnd = fminf(bnd, p.y - loy);
        if (hiy < 1.f) bnd = fminf(bnd, hiy - p.y);
        if (bnd == 3.402823466e+38f) break;
        if (bidx != 0x7fffffff && best < bnd * bnd * 0.99999f) break;
        ++r;
        scan_square(p, starts, pts, qcx, qcy, r, best, bidx);
    }

    float yt_off = yc_off[(size_t)b * NN + bidx];

    float lg  = logit[0];
    float mix = 1.0f / (1.0f + expf(-lg));
    out[(size_t)b * MM + m] = mix * yt_off + (1.0f - mix) * yt_on;
}

extern "C" void kernel_launch(void* const* d_in, const int* in_sizes, int n_in,
                              void* d_out, int out_size) {
    const float* xc_off = (const float*)d_in[0];  // (8,8192,2)
    const float* yc_off = (const float*)d_in[1];  // (8,8192)
    // d_in[2] = xc_on_grid (unused: analytic uniform grid)
    const float* yc_on  = (const float*)d_in[3];  // (8,128,128)
    const float* xt     = (const float*)d_in[4];  // (8,4096,2)
    const float* logit  = (const float*)d_in[5];  // scalar
    float* out = (float*)d_out;

    const int qgrid = (BB * MM + QPB - 1) / QPB;  // 152 blocks, one wave
    build_kernel<<<BB * 2, BTPB>>>(xc_off, yc_on, xt);
    query_kernel<<<qgrid, QTPB>>>(yc_off, yc_on, logit, out);
}

// round 8
// speedup vs baseline: 1.2459x; 1.2459x over previous
#include <cuda_runtime.h>
#include <math.h>

#define BB 8
#define NN 8192
#define MM 4096
#define HH 128
#define WW 128

#define G    64
#define GC   (G * G)           // 4096 cells per batch
#define BTPB 1024
#define PPT  (NN / BTPB)       // 8 points per thread
#define QPT  (MM / BTPB)       // 4 queries per thread
#define CPT  (GC / BTPB)       // 4 cells per thread

#define R    4                 // lanes per query
#define QTPB 256

__device__ float  g_mean[BB];
__device__ int    g_starts[BB * (GC + 1)];
__device__ float4 g_pts[BB * NN];   // cell-sorted points: x, y, 0, orig-idx bits
__device__ float4 g_q[BB * MM];     // cell-sorted queries: x, y, 0, orig-m bits

__device__ __forceinline__ int cell_of(float v) {
    int c = (int)(v * (float)G);
    return min(max(c, 0), G - 1);
}

// exclusive scan of GC counts in scnt[], leaves cursors in scnt, optionally writes starts
__device__ __forceinline__ void scan_counts(int* scnt, int* swscan, int tid,
                                            int lane, int wrp, int* starts) {
    int cnt[CPT], cur[CPT];
    int sum = 0;
    #pragma unroll
    for (int i = 0; i < CPT; ++i) { cnt[i] = scnt[tid * CPT + i]; sum += cnt[i]; }

    int v = sum;
    #pragma unroll
    for (int o = 1; o < 32; o <<= 1) {
        int n = __shfl_up_sync(0xffffffffu, v, o);
        if (lane >= o) v += n;
    }
    if (lane == 31) swscan[wrp] = v;
    __syncthreads();
    if (tid < 32) {
        int w = swscan[tid];
        #pragma unroll
        for (int o = 1; o < 32; o <<= 1) {
            int n = __shfl_up_sync(0xffffffffu, w, o);
            if (tid >= o) w += n;
        }
        swscan[tid] = w;
    }
    __syncthreads();
    int off = v - sum + (wrp ? swscan[wrp - 1] : 0);

    #pragma unroll
    for (int i = 0; i < CPT; ++i) {
        if (starts) starts[tid * CPT + i] = off;
        cur[i] = off;
        off += cnt[i];
    }
    __syncthreads();
    #pragma unroll
    for (int i = 0; i < CPT; ++i) scnt[tid * CPT + i] = cur[i];
    __syncthreads();
}

// ---------- build: 2 independent blocks per batch ----------
__global__ void __launch_bounds__(BTPB) build_kernel(
    const float* __restrict__ xc_off,   // (B,N,2)
    const float* __restrict__ yc_on,    // (B,H,W)
    const float* __restrict__ xt)       // (B,M,2)
{
    const int b    = blockIdx.x >> 1;
    const int role = blockIdx.x & 1;
    const int tid  = threadIdx.x;
    const int lane = tid & 31, wrp = tid >> 5;

    __shared__ int scnt[GC];
    __shared__ int swscan[32];

    #pragma unroll
    for (int i = 0; i < CPT; ++i) scnt[tid + i * BTPB] = 0;

    if (role == 0) {
        float2 pt[PPT];
        int    pc[PPT];
        const float2* cpts = (const float2*)(xc_off + (size_t)b * NN * 2);
        #pragma unroll
        for (int k = 0; k < PPT; ++k) {
            pt[k] = cpts[tid + k * BTPB];
            pc[k] = cell_of(pt[k].x) * G + cell_of(pt[k].y);
        }
        __syncthreads();
        #pragma unroll
        for (int k = 0; k < PPT; ++k) atomicAdd(&scnt[pc[k]], 1);
        __syncthreads();

        scan_counts(scnt, swscan, tid, lane, wrp, g_starts + b * (GC + 1));
        if (tid == 0) g_starts[b * (GC + 1) + GC] = NN;

        float4* dst = g_pts + (size_t)b * NN;
        #pragma unroll
        for (int k = 0; k < PPT; ++k) {
            int pos = atomicAdd(&scnt[pc[k]], 1);
            dst[pos] = make_float4(pt[k].x, pt[k].y, 0.f, __int_as_float(tid + k * BTPB));
        }
    } else {
        __shared__ float swsum[32];
        {
            const float* p = yc_on + (size_t)b * HH * WW;
            float s = 0.f;
            #pragma unroll
            for (int k = 0; k < (HH * WW) / BTPB; ++k) s += p[tid + k * BTPB];
            #pragma unroll
            for (int o = 16; o; o >>= 1) s += __shfl_down_sync(0xffffffffu, s, o);
            if (lane == 0) swsum[wrp] = s;
        }

        float2 qt[QPT];
        int    qc[QPT];
        const float2* q = (const float2*)(xt + (size_t)b * MM * 2);
        #pragma unroll
        for (int k = 0; k < QPT; ++k) {
            qt[k] = q[tid + k * BTPB];
            qc[k] = cell_of(qt[k].x) * G + cell_of(qt[k].y);
        }
        __syncthreads();
        if (tid < 32) {
            float s = swsum[tid];
            #pragma unroll
            for (int o = 16; o; o >>= 1) s += __shfl_down_sync(0xffffffffu, s, o);
            if (tid == 0) g_mean[b] = s * (1.0f / (HH * WW));
        }
        #pragma unroll
        for (int k = 0; k < QPT; ++k) atomicAdd(&scnt[qc[k]], 1);
        __syncthreads();

        scan_counts(scnt, swscan, tid, lane, wrp, (int*)0);

        float4* dst = g_q + (size_t)b * MM;
        #pragma unroll
        for (int k = 0; k < QPT; ++k) {
            int pos = atomicAdd(&scnt[qc[k]], 1);
            dst[pos] = make_float4(qt[k].x, qt[k].y, 0.f, __int_as_float(tid + k * BTPB));
        }
    }
}

// scan square of half-width r, this lane handles k = s+sub, s+sub+R, ...
// (4 lanes of a group cover each row segment with coalesced float4 loads)
__device__ __forceinline__ void scan_square_strided(
    const float2 p, const int* __restrict__ starts, const float4* __restrict__ pts,
    int qcx, int qcy, int r, int sub, float& best, int& bidx)
{
    const int ilo = max(qcx - r, 0), ihi = min(qcx + r, G - 1);
    const int jlo = max(qcy - r, 0), jhi = min(qcy + r, G - 1);
    int i = ilo;
    int s = starts[i * G + jlo];
    int e = starts[i * G + jhi + 1];
    for (;;) {
        const bool more = (i < ihi);
        int sn = 0, en = 0;
        if (more) {                       // prefetch next row's bounds
            sn = starts[(i + 1) * G + jlo];
            en = starts[(i + 1) * G + jhi + 1];
        }
        for (int k = s + sub; k < e; k += R) {
            float4 c = pts[k];
            float dx = p.x - c.x;
            float dy = p.y - c.y;
            float d2 = __fadd_rn(__fmul_rn(dx, dx), __fmul_rn(dy, dy));
            int   idx = __float_as_int(c.w);
            if (d2 < best || (d2 == best && idx < bidx)) { best = d2; bidx = idx; }
        }
        if (!more) break;
        s = sn; e = en; ++i;
    }
}

// lexicographic (d2, idx) min across the 4-lane group; exact & deterministic
__device__ __forceinline__ void merge4(float& best, int& bidx) {
    #pragma unroll
    for (int o = 1; o < R; o <<= 1) {
        float od2 = __shfl_xor_sync(0xffffffffu, best, o);
        int   oid = __shfl_xor_sync(0xffffffffu, bidx, o);
        if (od2 < best || (od2 == best && oid < bidx)) { best = od2; bidx = oid; }
    }
}

// ---------------- query: 4 lanes per sorted query ----------------
__global__ void __launch_bounds__(QTPB) query_kernel(
    const float* __restrict__ yc_off,
    const float* __restrict__ yc_on,
    const float* __restrict__ logit,
    float* __restrict__ out)
{
    const int gt  = blockIdx.x * QTPB + threadIdx.x;
    const int t   = gt / R;              // query index (sorted order)
    const int sub = gt & (R - 1);
    const int b   = t / MM;

    const float4 q = g_q[t];             // broadcast across the 4-lane group
    const float2 p = make_float2(q.x, q.y);
    const int    m = __float_as_int(q.w);

    const int*    starts = g_starts + b * (GC + 1);
    const float4* pts    = g_pts + (size_t)b * NN;

    // ---- bilinear (lane 0 of each group; loads overlap the NN scan) ----
    float yt_on = 0.f;
    if (sub == 0) {
        float x = p.x, y = p.y;
        bool oob = (x < 0.0f) || (x > 1.0f) || (y < 0.0f) || (y > 1.0f);
        float fx = x * 127.0f;
        float fy = y * 127.0f;
        int ix = (int)floorf(fx);
        int iy = (int)floorf(fy);
        ix = min(max(ix, 0), 126);
        iy = min(max(iy, 0), 126);
        float wx = fx - (float)ix;
        float wy = fy - (float)iy;

        const float* vv = yc_on + ((size_t)b * HH + ix) * WW + iy;
        float v00 = vv[0];
        float v01 = vv[1];
        float v10 = vv[WW];
        float v11 = vv[WW + 1];

        yt_on = (1.0f - wx) * (1.0f - wy) * v00
              + (1.0f - wx) * wy          * v01
              + wx          * (1.0f - wy) * v10
              + wx          * wy          * v11;
        if (oob) yt_on = g_mean[b];
    }

    const float h = 1.0f / (float)G;
    const int qcx = cell_of(p.x);
    const int qcy = cell_of(p.y);

    float best = 3.402823466e+38f;
    int   bidx = 0x7fffffff;

    // initial half-width: NN distance >= distance from p to [0,1]^2
    int r;
    {
        float dx0 = fmaxf(fmaxf(-p.x, p.x - 1.0f), 0.0f);
        float dy0 = fmaxf(fmaxf(-p.y, p.y - 1.0f), 0.0f);
        float d0sq = dx0 * dx0 + dy0 * dy0;
        r = 1;
        if (d0sq > 0.0f) r = (int)ceilf(sqrtf(d0sq) * (float)G) + 2;
        r = min(r, G);
    }

    scan_square_strided(p, starts, pts, qcx, qcy, r, sub, best, bidx);
    merge4(best, bidx);

    // bound-certify; rare expansion rescans grown square (idempotent comparator)
    for (;;) {
        float lox = (float)(qcx - r) * h,  hix = (float)(qcx + r + 1) * h;
        float loy = (float)(qcy - r) * h,  hiy = (float)(qcy + r + 1) * h;
        float bnd = 3.402823466e+38f;
        if (lox > 0.f) bnd = fminf(bnd, p.x - lox);
        if (hix < 1.f) bnd = fminf(bnd, hix - p.x);
        if (loy > 0.f) bnd = fminf(bnd, p.y - loy);
        if (hiy < 1.f) bnd = fminf(bnd, hiy - p.y);
        if (bnd == 3.402823466e+38f) break;
        if (bidx != 0x7fffffff && best < bnd * bnd * 0.99999f) break;
        ++r;
        scan_square_strided(p, starts, pts, qcx, qcy, r, sub, best, bidx);
        merge4(best, bidx);
    }

    if (sub == 0) {
        float yt_off = yc_off[(size_t)b * NN + bidx];
        float lg  = logit[0];
        float mix = 1.0f / (1.0f + expf(-lg));
        out[(size_t)b * MM + m] = mix * yt_off + (1.0f - mix) * yt_on;
    }
}

extern "C" void kernel_launch(void* const* d_in, const int* in_sizes, int n_in,
                              void* d_out, int out_size) {
    const float* xc_off = (const float*)d_in[0];  // (8,8192,2)
    const float* yc_off = (const float*)d_in[1];  // (8,8192)
    // d_in[2] = xc_on_grid (unused: analytic uniform grid)
    const float* yc_on  = (const float*)d_in[3];  // (8,128,128)
    const float* xt     = (const float*)d_in[4];  // (8,4096,2)
    const float* logit  = (const float*)d_in[5];  // scalar
    float* out = (float*)d_out;

    build_kernel<<<BB * 2, BTPB>>>(xc_off, yc_on, xt);
    query_kernel<<<(BB * MM * R) / QTPB, QTPB>>>(yc_off, yc_on, logit, out);
}

// round 9
// speedup vs baseline: 1.2951x; 1.0395x over previous
#include <cuda_runtime.h>
#include <math.h>

#define BB 8
#define NN 8192
#define MM 4096
#define HH 128
#define WW 128

#define G    64
#define GC   (G * G)           // 4096 cells per batch
#define BTPB 1024
#define PPT  (NN / BTPB)       // 8 points per thread
#define QPT  (MM / BTPB)       // 4 queries per thread
#define CPT  (GC / BTPB)       // 4 cells per thread

#define R    8                 // lanes per query
#define QTPB 256

__device__ float  g_mean[BB];
__device__ int    g_starts[BB * (GC + 1)];
__device__ float4 g_pts[BB * NN];   // cell-sorted points: x, y, 0, orig-idx bits
__device__ float4 g_q[BB * MM];     // cell-sorted queries: x, y, 0, orig-m bits

__device__ __forceinline__ int cell_of(float v) {
    int c = (int)(v * (float)G);
    return min(max(c, 0), G - 1);
}

// exclusive scan of GC counts in scnt[], leaves cursors in scnt, optionally writes starts
__device__ __forceinline__ void scan_counts(int* scnt, int* swscan, int tid,
                                            int lane, int wrp, int* starts) {
    int cnt[CPT], cur[CPT];
    int sum = 0;
    #pragma unroll
    for (int i = 0; i < CPT; ++i) { cnt[i] = scnt[tid * CPT + i]; sum += cnt[i]; }

    int v = sum;
    #pragma unroll
    for (int o = 1; o < 32; o <<= 1) {
        int n = __shfl_up_sync(0xffffffffu, v, o);
        if (lane >= o) v += n;
    }
    if (lane == 31) swscan[wrp] = v;
    __syncthreads();
    if (tid < 32) {
        int w = swscan[tid];
        #pragma unroll
        for (int o = 1; o < 32; o <<= 1) {
            int n = __shfl_up_sync(0xffffffffu, w, o);
            if (tid >= o) w += n;
        }
        swscan[tid] = w;
    }
    __syncthreads();
    int off = v - sum + (wrp ? swscan[wrp - 1] : 0);

    #pragma unroll
    for (int i = 0; i < CPT; ++i) {
        if (starts) starts[tid * CPT + i] = off;
        cur[i] = off;
        off += cnt[i];
    }
    __syncthreads();
    #pragma unroll
    for (int i = 0; i < CPT; ++i) scnt[tid * CPT + i] = cur[i];
    __syncthreads();
}

// ---------- build: 2 independent blocks per batch ----------
__global__ void __launch_bounds__(BTPB) build_kernel(
    const float* __restrict__ xc_off,   // (B,N,2)
    const float* __restrict__ yc_on,    // (B,H,W)
    const float* __restrict__ xt)       // (B,M,2)
{
    const int b    = blockIdx.x >> 1;
    const int role = blockIdx.x & 1;
    const int tid  = threadIdx.x;
    const int lane = tid & 31, wrp = tid >> 5;

    __shared__ int scnt[GC];
    __shared__ int swscan[32];

    #pragma unroll
    for (int i = 0; i < CPT; ++i) scnt[tid + i * BTPB] = 0;

    if (role == 0) {
        float2 pt[PPT];
        int    pc[PPT];
        const float2* cpts = (const float2*)(xc_off + (size_t)b * NN * 2);
        #pragma unroll
        for (int k = 0; k < PPT; ++k) {
            pt[k] = cpts[tid + k * BTPB];
            pc[k] = cell_of(pt[k].x) * G + cell_of(pt[k].y);
        }
        __syncthreads();
        #pragma unroll
        for (int k = 0; k < PPT; ++k) atomicAdd(&scnt[pc[k]], 1);
        __syncthreads();

        scan_counts(scnt, swscan, tid, lane, wrp, g_starts + b * (GC + 1));
        if (tid == 0) g_starts[b * (GC + 1) + GC] = NN;

        float4* dst = g_pts + (size_t)b * NN;
        #pragma unroll
        for (int k = 0; k < PPT; ++k) {
            int pos = atomicAdd(&scnt[pc[k]], 1);
            dst[pos] = make_float4(pt[k].x, pt[k].y, 0.f, __int_as_float(tid + k * BTPB));
        }
    } else {
        __shared__ float swsum[32];
        {
            const float* p = yc_on + (size_t)b * HH * WW;
            float s = 0.f;
            #pragma unroll
            for (int k = 0; k < (HH * WW) / BTPB; ++k) s += p[tid + k * BTPB];
            #pragma unroll
            for (int o = 16; o; o >>= 1) s += __shfl_down_sync(0xffffffffu, s, o);
            if (lane == 0) swsum[wrp] = s;
        }

        float2 qt[QPT];
        int    qc[QPT];
        const float2* q = (const float2*)(xt + (size_t)b * MM * 2);
        #pragma unroll
        for (int k = 0; k < QPT; ++k) {
            qt[k] = q[tid + k * BTPB];
            qc[k] = cell_of(qt[k].x) * G + cell_of(qt[k].y);
        }
        __syncthreads();
        if (tid < 32) {
            float s = swsum[tid];
            #pragma unroll
            for (int o = 16; o; o >>= 1) s += __shfl_down_sync(0xffffffffu, s, o);
            if (tid == 0) g_mean[b] = s * (1.0f / (HH * WW));
        }
        #pragma unroll
        for (int k = 0; k < QPT; ++k) atomicAdd(&scnt[qc[k]], 1);
        __syncthreads();

        scan_counts(scnt, swscan, tid, lane, wrp, (int*)0);

        float4* dst = g_q + (size_t)b * MM;
        #pragma unroll
        for (int k = 0; k < QPT; ++k) {
            int pos = atomicAdd(&scnt[qc[k]], 1);
            dst[pos] = make_float4(qt[k].x, qt[k].y, 0.f, __int_as_float(tid + k * BTPB));
        }
    }
}

// scan square of half-width r, this lane handles k = s+sub, s+sub+R, ...
__device__ __forceinline__ void scan_square_strided(
    const float2 p, const int* __restrict__ starts, const float4* __restrict__ pts,
    int qcx, int qcy, int r, int sub, float& best, int& bidx)
{
    const int ilo = max(qcx - r, 0), ihi = min(qcx + r, G - 1);
    const int jlo = max(qcy - r, 0), jhi = min(qcy + r, G - 1);
    int i = ilo;
    int s = starts[i * G + jlo];
    int e = starts[i * G + jhi + 1];
    for (;;) {
        const bool more = (i < ihi);
        int sn = 0, en = 0;
        if (more) {                       // prefetch next row's bounds
            sn = starts[(i + 1) * G + jlo];
            en = starts[(i + 1) * G + jhi + 1];
        }
        for (int k = s + sub; k < e; k += R) {
            float4 c = pts[k];
            float dx = p.x - c.x;
            float dy = p.y - c.y;
            float d2 = __fadd_rn(__fmul_rn(dx, dx), __fmul_rn(dy, dy));
            int   idx = __float_as_int(c.w);
            if (d2 < best || (d2 == best && idx < bidx)) { best = d2; bidx = idx; }
        }
        if (!more) break;
        s = sn; e = en; ++i;
    }
}

// lexicographic (d2, idx) min across the R-lane group; exact & deterministic
__device__ __forceinline__ void mergeR(float& best, int& bidx) {
    #pragma unroll
    for (int o = 1; o < R; o <<= 1) {
        float od2 = __shfl_xor_sync(0xffffffffu, best, o);
        int   oid = __shfl_xor_sync(0xffffffffu, bidx, o);
        if (od2 < best || (od2 == best && oid < bidx)) { best = od2; bidx = oid; }
    }
}

// ---------------- query: R lanes per sorted query ----------------
__global__ void __launch_bounds__(QTPB) query_kernel(
    const float* __restrict__ yc_off,
    const float* __restrict__ yc_on,
    const float* __restrict__ logit,
    float* __restrict__ out)
{
    const int gt  = blockIdx.x * QTPB + threadIdx.x;
    const int t   = gt / R;              // query index (sorted order)
    const int sub = gt & (R - 1);
    const int b   = t / MM;

    const float4 q = g_q[t];             // broadcast across the group
    const float2 p = make_float2(q.x, q.y);
    const int    m = __float_as_int(q.w);

    const int*    starts = g_starts + b * (GC + 1);
    const float4* pts    = g_pts + (size_t)b * NN;

    // ---- bilinear: 4 corner loads spread over lanes 0..3 of the group ----
    float x = p.x, y = p.y;
    float fx = x * 127.0f;
    float fy = y * 127.0f;
    int ix = (int)floorf(fx);
    int iy = (int)floorf(fy);
    ix = min(max(ix, 0), 126);
    iy = min(max(iy, 0), 126);

    float vcorner = 0.f;
    {
        // lane sub<4 loads corner (sub>>1, sub&1): v[di][dj]
        int di = (sub >> 1) & 1;
        int dj = sub & 1;
        vcorner = yc_on[((size_t)b * HH + ix + di) * WW + (iy + dj)];
    }
    // gather corners to every lane (group-aligned shuffles)
    const int lane = threadIdx.x & 31;
    const int gbase = lane & ~(R - 1);
    float v00 = __shfl_sync(0xffffffffu, vcorner, gbase + 0);
    float v01 = __shfl_sync(0xffffffffu, vcorner, gbase + 1);
    float v10 = __shfl_sync(0xffffffffu, vcorner, gbase + 2);
    float v11 = __shfl_sync(0xffffffffu, vcorner, gbase + 3);

    const float h = 1.0f / (float)G;
    const int qcx = cell_of(p.x);
    const int qcy = cell_of(p.y);

    float best = 3.402823466e+38f;
    int   bidx = 0x7fffffff;

    // initial half-width: NN distance >= distance from p to [0,1]^2
    int r;
    {
        float dx0 = fmaxf(fmaxf(-p.x, p.x - 1.0f), 0.0f);
        float dy0 = fmaxf(fmaxf(-p.y, p.y - 1.0f), 0.0f);
        float d0sq = dx0 * dx0 + dy0 * dy0;
        r = 1;
        if (d0sq > 0.0f) r = (int)ceilf(sqrtf(d0sq) * (float)G) + 2;
        r = min(r, G);
    }

    scan_square_strided(p, starts, pts, qcx, qcy, r, sub, best, bidx);
    mergeR(best, bidx);

    // bound-certify; rare expansion rescans grown square (idempotent comparator)
    for (;;) {
        float lox = (float)(qcx - r) * h,  hix = (float)(qcx + r + 1) * h;
        float loy = (float)(qcy - r) * h,  hiy = (float)(qcy + r + 1) * h;
        float bnd = 3.402823466e+38f;
        if (lox > 0.f) bnd = fminf(bnd, p.x - lox);
        if (hix < 1.f) bnd = fminf(bnd, hix - p.x);
        if (loy > 0.f) bnd = fminf(bnd, p.y - loy);
        if (hiy < 1.f) bnd = fminf(bnd, hiy - p.y);
        if (bnd == 3.402823466e+38f) break;
        if (bidx != 0x7fffffff && best < bnd * bnd * 0.99999f) break;
        ++r;
        scan_square_strided(p, starts, pts, qcx, qcy, r, sub, best, bidx);
        mergeR(best, bidx);
    }

    if (sub == 0) {
        // identical arithmetic to previous rounds (lane 0 evaluates full expr)
        bool oob = (x < 0.0f) || (x > 1.0f) || (y < 0.0f) || (y > 1.0f);
        float wx = fx - (float)ix;
        float wy = fy - (float)iy;
        float yt_on = (1.0f - wx) * (1.0f - wy) * v00
                    + (1.0f - wx) * wy          * v01
                    + wx          * (1.0f - wy) * v10
                    + wx          * wy          * v11;
        if (oob) yt_on = g_mean[b];

        float yt_off = yc_off[(size_t)b * NN + bidx];
        float lg  = logit[0];
        float mix = 1.0f / (1.0f + expf(-lg));
        out[(size_t)b * MM + m] = mix * yt_off + (1.0f - mix) * yt_on;
    }
}

extern "C" void kernel_launch(void* const* d_in, const int* in_sizes, int n_in,
                              void* d_out, int out_size) {
    const float* xc_off = (const float*)d_in[0];  // (8,8192,2)
    const float* yc_off = (const float*)d_in[1];  // (8,8192)
    // d_in[2] = xc_on_grid (unused: analytic uniform grid)
    const float* yc_on  = (const float*)d_in[3];  // (8,128,128)
    const float* xt     = (const float*)d_in[4];  // (8,4096,2)
    const float* logit  = (const float*)d_in[5];  // scalar
    float* out = (float*)d_out;

    build_kernel<<<BB * 2, BTPB>>>(xc_off, yc_on, xt);
    query_kernel<<<(BB * MM * R) / QTPB, QTPB>>>(yc_off, yc_on, logit, out);
}

// round 10
// speedup vs baseline: 1.4827x; 1.1448x over previous
#include <cuda_runtime.h>
#include <math.h>

#define BB 8
#define NN 8192
#define MM 4096
#define HH 128
#define WW 128

#define G    64
#define GC   (G * G)           // 4096 cells per batch
#define BTPB 1024
#define PPT  (NN / BTPB)       // 8 points per thread
#define QPT  (MM / BTPB)       // 4 queries per thread
#define CPT  (GC / BTPB)       // 4 cells per thread

#define R    4                 // lanes per query
#define QTPB 256

__device__ float  g_mean[BB];
__device__ int    g_starts[BB * (GC + 1)];
__device__ float4 g_pts[BB * NN];   // cell-sorted points: x, y, 0, orig-idx bits
__device__ float4 g_q[BB * MM];     // cell-sorted queries: x, y, 0, orig-m bits

__device__ __forceinline__ int cell_of(float v) {
    int c = (int)(v * (float)G);
    return min(max(c, 0), G - 1);
}

// exclusive scan of GC counts in scnt[], leaves cursors in scnt, optionally writes starts
__device__ __forceinline__ void scan_counts(int* scnt, int* swscan, int tid,
                                            int lane, int wrp, int* starts) {
    int cnt[CPT], cur[CPT];
    int sum = 0;
    #pragma unroll
    for (int i = 0; i < CPT; ++i) { cnt[i] = scnt[tid * CPT + i]; sum += cnt[i]; }

    int v = sum;
    #pragma unroll
    for (int o = 1; o < 32; o <<= 1) {
        int n = __shfl_up_sync(0xffffffffu, v, o);
        if (lane >= o) v += n;
    }
    if (lane == 31) swscan[wrp] = v;
    __syncthreads();
    if (tid < 32) {
        int w = swscan[tid];
        #pragma unroll
        for (int o = 1; o < 32; o <<= 1) {
            int n = __shfl_up_sync(0xffffffffu, w, o);
            if (tid >= o) w += n;
        }
        swscan[tid] = w;
    }
    __syncthreads();
    int off = v - sum + (wrp ? swscan[wrp - 1] : 0);

    #pragma unroll
    for (int i = 0; i < CPT; ++i) {
        if (starts) starts[tid * CPT + i] = off;
        cur[i] = off;
        off += cnt[i];
    }
    __syncthreads();
    #pragma unroll
    for (int i = 0; i < CPT; ++i) scnt[tid * CPT + i] = cur[i];
    __syncthreads();
}

// ---------- build: 2 independent blocks per batch ----------
__global__ void __launch_bounds__(BTPB) build_kernel(
    const float* __restrict__ xc_off,   // (B,N,2)
    const float* __restrict__ yc_on,    // (B,H,W)
    const float* __restrict__ xt)       // (B,M,2)
{
    const int b    = blockIdx.x >> 1;
    const int role = blockIdx.x & 1;
    const int tid  = threadIdx.x;
    const int lane = tid & 31, wrp = tid >> 5;

    __shared__ int scnt[GC];
    __shared__ int swscan[32];

    #pragma unroll
    for (int i = 0; i < CPT; ++i) scnt[tid + i * BTPB] = 0;

    if (role == 0) {
        float2 pt[PPT];
        int    pc[PPT];
        const float2* cpts = (const float2*)(xc_off + (size_t)b * NN * 2);
        #pragma unroll
        for (int k = 0; k < PPT; ++k) {
            pt[k] = cpts[tid + k * BTPB];
            pc[k] = cell_of(pt[k].x) * G + cell_of(pt[k].y);
        }
        __syncthreads();
        #pragma unroll
        for (int k = 0; k < PPT; ++k) atomicAdd(&scnt[pc[k]], 1);
        __syncthreads();

        scan_counts(scnt, swscan, tid, lane, wrp, g_starts + b * (GC + 1));
        if (tid == 0) g_starts[b * (GC + 1) + GC] = NN;

        float4* dst = g_pts + (size_t)b * NN;
        #pragma unroll
        for (int k = 0; k < PPT; ++k) {
            int pos = atomicAdd(&scnt[pc[k]], 1);
            dst[pos] = make_float4(pt[k].x, pt[k].y, 0.f, __int_as_float(tid + k * BTPB));
        }
    } else {
        __shared__ float swsum[32];
        {
            const float* p = yc_on + (size_t)b * HH * WW;
            float s = 0.f;
            #pragma unroll
            for (int k = 0; k < (HH * WW) / BTPB; ++k) s += p[tid + k * BTPB];
            #pragma unroll
            for (int o = 16; o; o >>= 1) s += __shfl_down_sync(0xffffffffu, s, o);
            if (lane == 0) swsum[wrp] = s;
        }

        float2 qt[QPT];
        int    qc[QPT];
        const float2* q = (const float2*)(xt + (size_t)b * MM * 2);
        #pragma unroll
        for (int k = 0; k < QPT; ++k) {
            qt[k] = q[tid + k * BTPB];
            qc[k] = cell_of(qt[k].x) * G + cell_of(qt[k].y);
        }
        __syncthreads();
        if (tid < 32) {
            float s = swsum[tid];
            #pragma unroll
            for (int o = 16; o; o >>= 1) s += __shfl_down_sync(0xffffffffu, s, o);
            if (tid == 0) g_mean[b] = s * (1.0f / (HH * WW));
        }
        #pragma unroll
        for (int k = 0; k < QPT; ++k) atomicAdd(&scnt[qc[k]], 1);
        __syncthreads();

        scan_counts(scnt, swscan, tid, lane, wrp, (int*)0);

        float4* dst = g_q + (size_t)b * MM;
        #pragma unroll
        for (int k = 0; k < QPT; ++k) {
            int pos = atomicAdd(&scnt[qc[k]], 1);
            dst[pos] = make_float4(qt[k].x, qt[k].y, 0.f, __int_as_float(tid + k * BTPB));
        }
    }
}

// scan cell window [ilo..ihi]x[jlo..jhi]; this lane takes k = s+sub, +R, ...
// rows are contiguous point segments; next-row bounds prefetched.
__device__ __forceinline__ void scan_window(
    const float2 p, const int* __restrict__ starts, const float4* __restrict__ pts,
    int ilo, int ihi, int jlo, int jhi, int sub, float& best, int& bidx)
{
    int i = ilo;
    int s = starts[i * G + jlo];
    int e = starts[i * G + jhi + 1];
    for (;;) {
        const bool more = (i < ihi);
        int sn = 0, en = 0;
        if (more) {
            sn = starts[(i + 1) * G + jlo];
            en = starts[(i + 1) * G + jhi + 1];
        }
        for (int k = s + sub; k < e; k += R) {
            float4 c = pts[k];
            float dx = p.x - c.x;
            float dy = p.y - c.y;
            float d2 = __fadd_rn(__fmul_rn(dx, dx), __fmul_rn(dy, dy));
            int   idx = __float_as_int(c.w);
            if (d2 < best || (d2 == best && idx < bidx)) { best = d2; bidx = idx; }
        }
        if (!more) break;
        s = sn; e = en; ++i;
    }
}

// lexicographic (d2, idx) min across the R-lane group; exact & deterministic
__device__ __forceinline__ void mergeR(float& best, int& bidx) {
    #pragma unroll
    for (int o = 1; o < R; o <<= 1) {
        float od2 = __shfl_xor_sync(0xffffffffu, best, o);
        int   oid = __shfl_xor_sync(0xffffffffu, bidx, o);
        if (od2 < best || (od2 == best && oid < bidx)) { best = od2; bidx = oid; }
    }
}

// ---------------- query: R lanes per sorted query, disk-cover certificate ----------------
__global__ void __launch_bounds__(QTPB) query_kernel(
    const float* __restrict__ yc_off,
    const float* __restrict__ yc_on,
    const float* __restrict__ logit,
    float* __restrict__ out)
{
    const int gt  = blockIdx.x * QTPB + threadIdx.x;
    const int t   = gt / R;              // query index (sorted order)
    const int sub = gt & (R - 1);
    const int b   = t / MM;

    const float4 q = g_q[t];             // broadcast across the group
    const float2 p = make_float2(q.x, q.y);
    const int    m = __float_as_int(q.w);

    const int*    starts = g_starts + b * (GC + 1);
    const float4* pts    = g_pts + (size_t)b * NN;

    // ---- bilinear index math + 4 corner loads spread over lanes 0..3 ----
    float x = p.x, y = p.y;
    float fx = x * 127.0f;
    float fy = y * 127.0f;
    int ix = (int)floorf(fx);
    int iy = (int)floorf(fy);
    ix = min(max(ix, 0), 126);
    iy = min(max(iy, 0), 126);

    float vcorner;
    {
        int di = (sub >> 1) & 1;
        int dj = sub & 1;
        vcorner = yc_on[((size_t)b * HH + ix + di) * WW + (iy + dj)];
    }
    const int lane  = threadIdx.x & 31;
    const int gbase = lane & ~(R - 1);
    float v00 = __shfl_sync(0xffffffffu, vcorner, gbase + 0);
    float v01 = __shfl_sync(0xffffffffu, vcorner, gbase + 1);
    float v10 = __shfl_sync(0xffffffffu, vcorner, gbase + 2);
    float v11 = __shfl_sync(0xffffffffu, vcorner, gbase + 3);

    const int qcx = cell_of(p.x);
    const int qcy = cell_of(p.y);

    float best = 3.402823466e+38f;
    int   bidx = 0x7fffffff;

    // initial window: 3x3 around clamped cell
    int ilo = max(qcx - 1, 0), ihi = min(qcx + 1, G - 1);
    int jlo = max(qcy - 1, 0), jhi = min(qcy + 1, G - 1);
    scan_window(p, starts, pts, ilo, ihi, jlo, jhi, sub, best, bidx);
    mergeR(best, bidx);

    // (essentially never taken) ensure at least one candidate
    while (bidx == 0x7fffffff) {
        ilo = max(ilo - 1, 0); ihi = min(ihi + 1, G - 1);
        jlo = max(jlo - 1, 0); jhi = min(jhi + 1, G - 1);
        scan_window(p, starts, pts, ilo, ihi, jlo, jhi, sub, best, bidx);
        mergeR(best, bidx);
        if (ilo == 0 && ihi == G - 1 && jlo == 0 && jhi == G - 1) break;
    }

    // disk-cover certificate: window must cover all cells intersecting the
    // disk of radius sqrt(best) around p (clamped to grid). Conservative
    // round-up sqrt + epsilon in cell units so no candidate (even an exact
    // tie) can lie outside the certified window.
    for (;;) {
        float rad = __fsqrt_ru(best);
        int nilo = max((int)floorf((p.x - rad) * (float)G - 1e-3f), 0);
        int nihi = min((int)floorf((p.x + rad) * (float)G + 1e-3f), G - 1);
        int njlo = max((int)floorf((p.y - rad) * (float)G - 1e-3f), 0);
        int njhi = min((int)floorf((p.y + rad) * (float)G + 1e-3f), G - 1);
        if (nilo >= ilo && nihi <= ihi && njlo >= jlo && njhi <= jhi) break;
        ilo = min(ilo, nilo); ihi = max(ihi, nihi);
        jlo = min(jlo, njlo); jhi = max(jhi, njhi);
        scan_window(p, starts, pts, ilo, ihi, jlo, jhi, sub, best, bidx);  // idempotent
        mergeR(best, bidx);
    }

    if (sub == 0) {
        bool oob = (x < 0.0f) || (x > 1.0f) || (y < 0.0f) || (y > 1.0f);
        float wx = fx - (float)ix;
        float wy = fy - (float)iy;
        float yt_on = (1.0f - wx) * (1.0f - wy) * v00
                    + (1.0f - wx) * wy          * v01
                    + wx          * (1.0f - wy) * v10
                    + wx          * wy          * v11;
        if (oob) yt_on = g_mean[b];

        float yt_off = yc_off[(size_t)b * NN + bidx];
        float lg  = logit[0];
        float mix = 1.0f / (1.0f + expf(-lg));
        out[(size_t)b * MM + m] = mix * yt_off + (1.0f - mix) * yt_on;
    }
}

extern "C" void kernel_launch(void* const* d_in, const int* in_sizes, int n_in,
                              void* d_out, int out_size) {
    const float* xc_off = (const float*)d_in[0];  // (8,8192,2)
    const float* yc_off = (const float*)d_in[1];  // (8,8192)
    // d_in[2] = xc_on_grid (unused: analytic uniform grid)
    const float* yc_on  = (const float*)d_in[3];  // (8,128,128)
    const float* xt     = (const float*)d_in[4];  // (8,4096,2)
    const float* logit  = (const float*)d_in[5];  // scalar
    float* out = (float*)d_out;

    build_kernel<<<BB * 2, BTPB>>>(xc_off, yc_on, xt);
    query_kernel<<<(BB * MM * R) / QTPB, QTPB>>>(yc_off, yc_on, logit, out);
}

// round 11
// speedup vs baseline: 1.5008x; 1.0122x over previous
#include <cuda_runtime.h>
#include <math.h>

#define BB 8
#define NN 8192
#define MM 4096
#define HH 128
#define WW 128

#define G    64
#define GC   (G * G)           // 4096 cells per batch
#define BTPB 1024
#define PPT  (NN / BTPB)       // 8 points per thread
#define QPT  (MM / BTPB)       // 4 queries per thread
#define CPT  (GC / BTPB)       // 4 cells per thread

#define R    4                 // lanes per query
#define QTPB 256

__device__ float  g_mean[BB];
__device__ int    g_starts[BB * (GC + 1)];
__device__ float4 g_pts[BB * NN];   // cell-sorted points: x, y, 0, orig-idx bits
__device__ float4 g_q[BB * MM];     // cell-sorted queries: x, y, 0, orig-m bits

__device__ __forceinline__ int cell_of(float v) {
    int c = (int)(v * (float)G);
    return min(max(c, 0), G - 1);
}

// exclusive scan of GC counts in scnt[]; leaves exclusive offsets in scnt,
// optionally mirrors them to g_starts.
__device__ __forceinline__ void scan_counts(int* scnt, int* swscan, int tid,
                                            int lane, int wrp, int* starts) {
    int cnt[CPT], cur[CPT];
    int sum = 0;
    #pragma unroll
    for (int i = 0; i < CPT; ++i) { cnt[i] = scnt[tid * CPT + i]; sum += cnt[i]; }

    int v = sum;
    #pragma unroll
    for (int o = 1; o < 32; o <<= 1) {
        int n = __shfl_up_sync(0xffffffffu, v, o);
        if (lane >= o) v += n;
    }
    if (lane == 31) swscan[wrp] = v;
    __syncthreads();
    if (tid < 32) {
        int w = swscan[tid];
        #pragma unroll
        for (int o = 1; o < 32; o <<= 1) {
            int n = __shfl_up_sync(0xffffffffu, w, o);
            if (tid >= o) w += n;
        }
        swscan[tid] = w;
    }
    __syncthreads();
    int off = v - sum + (wrp ? swscan[wrp - 1] : 0);

    #pragma unroll
    for (int i = 0; i < CPT; ++i) {
        if (starts) starts[tid * CPT + i] = off;
        cur[i] = off;
        off += cnt[i];
    }
    __syncthreads();
    #pragma unroll
    for (int i = 0; i < CPT; ++i) scnt[tid * CPT + i] = cur[i];
    __syncthreads();
}

// ---------- build: 2 independent blocks per batch, single-atomic binning ----------
__global__ void __launch_bounds__(BTPB) build_kernel(
    const float* __restrict__ xc_off,   // (B,N,2)
    const float* __restrict__ yc_on,    // (B,H,W)
    const float* __restrict__ xt)       // (B,M,2)
{
    const int b    = blockIdx.x >> 1;
    const int role = blockIdx.x & 1;
    const int tid  = threadIdx.x;
    const int lane = tid & 31, wrp = tid >> 5;

    __shared__ int scnt[GC];
    __shared__ int swscan[32];

    #pragma unroll
    for (int i = 0; i < CPT; ++i) scnt[tid + i * BTPB] = 0;

    if (role == 0) {
        float2 pt[PPT];
        int    pc[PPT], rk[PPT];
        const float2* cpts = (const float2*)(xc_off + (size_t)b * NN * 2);
        #pragma unroll
        for (int k = 0; k < PPT; ++k) {
            pt[k] = cpts[tid + k * BTPB];
            pc[k] = cell_of(pt[k].x) * G + cell_of(pt[k].y);
        }
        __syncthreads();   // zeroed histogram visible
        #pragma unroll
        for (int k = 0; k < PPT; ++k) rk[k] = atomicAdd(&scnt[pc[k]], 1);  // rank in cell
        __syncthreads();

        scan_counts(scnt, swscan, tid, lane, wrp, g_starts + b * (GC + 1));
        if (tid == 0) g_starts[b * (GC + 1) + GC] = NN;

        float4* dst = g_pts + (size_t)b * NN;
        #pragma unroll
        for (int k = 0; k < PPT; ++k) {
            int pos = scnt[pc[k]] + rk[k];           // no second atomic pass
            dst[pos] = make_float4(pt[k].x, pt[k].y, 0.f, __int_as_float(tid + k * BTPB));
        }
    } else {
        __shared__ float swsum[32];
        {
            const float* p = yc_on + (size_t)b * HH * WW;
            float s = 0.f;
            #pragma unroll
            for (int k = 0; k < (HH * WW) / BTPB; ++k) s += p[tid + k * BTPB];
            #pragma unroll
            for (int o = 16; o; o >>= 1) s += __shfl_down_sync(0xffffffffu, s, o);
            if (lane == 0) swsum[wrp] = s;
        }

        float2 qt[QPT];
        int    qc[QPT], rk[QPT];
        const float2* q = (const float2*)(xt + (size_t)b * MM * 2);
        #pragma unroll
        for (int k = 0; k < QPT; ++k) {
            qt[k] = q[tid + k * BTPB];
            qc[k] = cell_of(qt[k].x) * G + cell_of(qt[k].y);
        }
        __syncthreads();
        if (tid < 32) {
            float s = swsum[tid];
            #pragma unroll
            for (int o = 16; o; o >>= 1) s += __shfl_down_sync(0xffffffffu, s, o);
            if (tid == 0) g_mean[b] = s * (1.0f / (HH * WW));
        }
        #pragma unroll
        for (int k = 0; k < QPT; ++k) rk[k] = atomicAdd(&scnt[qc[k]], 1);
        __syncthreads();

        scan_counts(scnt, swscan, tid, lane, wrp, (int*)0);

        float4* dst = g_q + (size_t)b * MM;
        #pragma unroll
        for (int k = 0; k < QPT; ++k) {
            int pos = scnt[qc[k]] + rk[k];
            dst[pos] = make_float4(qt[k].x, qt[k].y, 0.f, __int_as_float(tid + k * BTPB));
        }
    }
}

// generic window scan (expansion path only); rows contiguous, per-row stride
__device__ __forceinline__ void scan_window(
    const float2 p, const int* __restrict__ starts, const float4* __restrict__ pts,
    int ilo, int ihi, int jlo, int jhi, int sub, float& best, int& bidx)
{
    for (int i = ilo; i <= ihi; ++i) {
        int s = starts[i * G + jlo];
        int e = starts[i * G + jhi + 1];
        for (int k = s + sub; k < e; k += R) {
            float4 c = pts[k];
            float dx = p.x - c.x;
            float dy = p.y - c.y;
            float d2 = __fadd_rn(__fmul_rn(dx, dx), __fmul_rn(dy, dy));
            int   idx = __float_as_int(c.w);
            if (d2 < best || (d2 == best && idx < bidx)) { best = d2; bidx = idx; }
        }
    }
}

// lexicographic (d2, idx) min across the R-lane group; exact & deterministic
__device__ __forceinline__ void mergeR(float& best, int& bidx) {
    #pragma unroll
    for (int o = 1; o < R; o <<= 1) {
        float od2 = __shfl_xor_sync(0xffffffffu, best, o);
        int   oid = __shfl_xor_sync(0xffffffffu, bidx, o);
        if (od2 < best || (od2 == best && oid < bidx)) { best = od2; bidx = oid; }
    }
}

// ---------------- query: R lanes per sorted query, disk-cover certificate ----------------
__global__ void __launch_bounds__(QTPB) query_kernel(
    const float* __restrict__ yc_off,
    const float* __restrict__ yc_on,
    const float* __restrict__ logit,
    float* __restrict__ out)
{
    const int gt  = blockIdx.x * QTPB + threadIdx.x;
    const int t   = gt / R;              // query index (sorted order)
    const int sub = gt & (R - 1);
    const int b   = t / MM;

    const float4 q = g_q[t];             // broadcast across the group
    const float2 p = make_float2(q.x, q.y);
    const int    m = __float_as_int(q.w);

    const int*    starts = g_starts + b * (GC + 1);
    const float4* pts    = g_pts + (size_t)b * NN;

    // ---- bilinear index math + 4 corner loads spread over lanes 0..3 ----
    float x = p.x, y = p.y;
    float fx = x * 127.0f;
    float fy = y * 127.0f;
    int ix = (int)floorf(fx);
    int iy = (int)floorf(fy);
    ix = min(max(ix, 0), 126);
    iy = min(max(iy, 0), 126);

    float vcorner;
    {
        int di = (sub >> 1) & 1;
        int dj = sub & 1;
        vcorner = yc_on[((size_t)b * HH + ix + di) * WW + (iy + dj)];
    }
    const int lane  = threadIdx.x & 31;
    const int gbase = lane & ~(R - 1);
    float v00 = __shfl_sync(0xffffffffu, vcorner, gbase + 0);
    float v01 = __shfl_sync(0xffffffffu, vcorner, gbase + 1);
    float v10 = __shfl_sync(0xffffffffu, vcorner, gbase + 2);
    float v11 = __shfl_sync(0xffffffffu, vcorner, gbase + 3);

    const int qcx = cell_of(p.x);
    const int qcy = cell_of(p.y);

    float best = 3.402823466e+38f;
    int   bidx = 0x7fffffff;

    // ---- initial 3x3 window: hoist ALL row bounds (one L2 wave), then
    //      flatten the row segments into one lane-strided virtual list ----
    int ilo = max(qcx - 1, 0), ihi = min(qcx + 1, G - 1);
    int jlo = max(qcy - 1, 0), jhi = min(qcy + 1, G - 1);
    {
        const int nrows = ihi - ilo + 1;
        int s0, e0, s1 = 0, e1 = 0, s2 = 0, e2 = 0;
        s0 = starts[ilo * G + jlo];
        e0 = starts[ilo * G + jhi + 1];
        if (nrows > 1) { s1 = starts[(ilo + 1) * G + jlo]; e1 = starts[(ilo + 1) * G + jhi + 1]; }
        if (nrows > 2) { s2 = starts[(ilo + 2) * G + jlo]; e2 = starts[(ilo + 2) * G + jhi + 1]; }
        const int l0 = e0 - s0, l1 = e1 - s1, l2 = e2 - s2;
        const int total = l0 + l1 + l2;

        for (int g = sub; g < total; g += R) {
            int k, g2 = g;
            if (g2 < l0)            k = s0 + g2;
            else { g2 -= l0;
                if (g2 < l1)        k = s1 + g2;
                else                k = s2 + (g2 - l1); }
            float4 c = pts[k];
            float dx = p.x - c.x;
            float dy = p.y - c.y;
            float d2 = __fadd_rn(__fmul_rn(dx, dx), __fmul_rn(dy, dy));
            int   idx = __float_as_int(c.w);
            if (d2 < best || (d2 == best && idx < bidx)) { best = d2; bidx = idx; }
        }
    }
    mergeR(best, bidx);

    // (essentially never taken) ensure at least one candidate
    while (bidx == 0x7fffffff) {
        ilo = max(ilo - 1, 0); ihi = min(ihi + 1, G - 1);
        jlo = max(jlo - 1, 0); jhi = min(jhi + 1, G - 1);
        scan_window(p, starts, pts, ilo, ihi, jlo, jhi, sub, best, bidx);
        mergeR(best, bidx);
        if (ilo == 0 && ihi == G - 1 && jlo == 0 && jhi == G - 1) break;
    }

    // disk-cover certificate: window must cover all cells intersecting the
    // disk of radius sqrt(best) around p (clamped). Round-up sqrt + eps so
    // no candidate (even an exact tie) can lie outside the certified window.
    for (;;) {
        float rad = __fsqrt_ru(best);
        int nilo = max((int)floorf((p.x - rad) * (float)G - 1e-3f), 0);
        int nihi = min((int)floorf((p.x + rad) * (float)G + 1e-3f), G - 1);
        int njlo = max((int)floorf((p.y - rad) * (float)G - 1e-3f), 0);
        int njhi = min((int)floorf((p.y + rad) * (float)G + 1e-3f), G - 1);
        if (nilo >= ilo && nihi <= ihi && njlo >= jlo && njhi <= jhi) break;
        ilo = min(ilo, nilo); ihi = max(ihi, nihi);
        jlo = min(jlo, njlo); jhi = max(jhi, njhi);
        scan_window(p, starts, pts, ilo, ihi, jlo, jhi, sub, best, bidx);  // idempotent
        mergeR(best, bidx);
    }

    if (sub == 0) {
        bool oob = (x < 0.0f) || (x > 1.0f) || (y < 0.0f) || (y > 1.0f);
        float wx = fx - (float)ix;
        float wy = fy - (float)iy;
        float yt_on = (1.0f - wx) * (1.0f - wy) * v00
                    + (1.0f - wx) * wy          * v01
                    + wx          * (1.0f - wy) * v10
                    + wx          * wy          * v11;
        if (oob) yt_on = g_mean[b];

        float yt_off = yc_off[(size_t)b * NN + bidx];
        float lg  = logit[0];
        float mix = 1.0f / (1.0f + expf(-lg));
        out[(size_t)b * MM + m] = mix * yt_off + (1.0f - mix) * yt_on;
    }
}

extern "C" void kernel_launch(void* const* d_in, const int* in_sizes, int n_in,
                              void* d_out, int out_size) {
    const float* xc_off = (const float*)d_in[0];  // (8,8192,2)
    const float* yc_off = (const float*)d_in[1];  // (8,8192)
    // d_in[2] = xc_on_grid (unused: analytic uniform grid)
    const float* yc_on  = (const float*)d_in[3];  // (8,128,128)
    const float* xt     = (const float*)d_in[4];  // (8,4096,2)
    const float* logit  = (const float*)d_in[5];  // scalar
    float* out = (float*)d_out;

    build_kernel<<<BB * 2, BTPB>>>(xc_off, yc_on, xt);
    query_kernel<<<(BB * MM * R) / QTPB, QTPB>>>(yc_off, yc_on, logit, out);
}